// round 10
// baseline (speedup 1.0000x reference)
#include <cuda_runtime.h>
#include <cuda_bf16.h>
#include <cstdint>

// CRFConstituency inside-outside, B=8, S=256, lens==255 (fixed triu mask).
// R9: widen the cluster. 16-CTA cluster per batch (grid=128), 512 threads/CTA,
// full 130,560-B smem replica of the packed inside triangle per CTA, one span
// per warp (sp = wid*16 + rank), barrier.cluster between width steps (proven
// fastest in R6; mbarrier and counter barriers both lost). Halves the
// issue-serialization per SMSP (4 warps instead of 8). Broadcast of each new
// value now uses lanes 0..15 (one st.shared::cluster per peer, single warp
// instruction) instead of a serial lane0 loop — butterfly reductions already
// leave the result in every lane.

#define SS 256
#define BB 8
#define CLUSTER 16
#define NTHREADS 512
#define TRI ((SS*(SS-1))/2)          // 32640 floats
#define SMEM_BYTES (TRI*4)           // 130560 bytes dynamic
#define NEGF (-1e30f)

__device__ float g_Ar[BB][SS][SS];
__device__ float g_Ac[BB][SS][SS];

__device__ __forceinline__ int tri_base(int i) {
    return i * (SS - 1) - ((i * (i - 1)) >> 1);
}

__device__ __forceinline__ uint32_t smem_u32(const void* p) {
    uint32_t a;
    asm("{ .reg .u64 t; cvta.to.shared.u64 t, %1; cvt.u32.u64 %0, t; }"
        : "=r"(a) : "l"(p));
    return a;
}

__device__ __forceinline__ void st_peer(uint32_t local_addr, int peer, float v) {
    uint32_t rem;
    asm volatile("mapa.shared::cluster.u32 %0, %1, %2;"
                 : "=r"(rem) : "r"(local_addr), "r"(peer));
    asm volatile("st.shared::cluster.f32 [%0], %1;" :: "r"(rem), "f"(v));
}

__device__ __forceinline__ void cluster_sync_all() {
    asm volatile("barrier.cluster.arrive.aligned;" ::: "memory");
    asm volatile("barrier.cluster.wait.aligned;" ::: "memory");
}

__global__ __launch_bounds__(NTHREADS, 1) __cluster_dims__(CLUSTER, 1, 1)
void crf_inside_outside_cluster(const float* __restrict__ scores,
                                float* __restrict__ out)
{
    extern __shared__ float s_tri[];     // full packed triangle replica

    const int b = blockIdx.x >> 4;       // cluster index = batch
    uint32_t rank;
    asm("mov.u32 %0, %%cluster_ctarank;" : "=r"(rank));

    const float* sc = scores + b * SS * SS;
    float* mout     = out    + b * SS * SS;

    const int tid  = threadIdx.x;
    const int lane = tid & 31;
    const int wid  = tid >> 5;           // 16 warps
    const int sp_of_warp = wid * CLUSTER + (int)rank;   // 0..255

    // ---------------- forward width-1 init (local replica) ----------------
    for (int i = tid; i < SS - 1; i += NTHREADS)
        s_tri[tri_base(i)] = sc[i * SS + i + 1];
    __syncthreads();
    cluster_sync_all();

    // ---------------- forward widths 2..255 ----------------
    for (int w = 2; w <= SS - 1; ++w) {
        const int nspans = SS - w;
        const int sp = sp_of_warp;
        if (sp < nspans) {
            const int i = sp;
            const int j = i + w;
            const int rb_i = tri_base(i);
            const int nch  = (w - 1 + 31) >> 5;

            const float scij = __ldca(&sc[i * SS + j]);   // hoisted off the tail

            int k0   = i + 1 + lane;
            int off1 = rb_i + lane;
            int off2 = tri_base(k0) + (j - k0 - 1);
            int kk   = k0;

            float tv[8];
            float mx = NEGF;
            #pragma unroll
            for (int c = 0; c < 8; ++c) {
                tv[c] = NEGF;
                if (c < nch) {
                    if (kk < j)
                        tv[c] = s_tri[off1] + s_tri[off2];
                    off1 += 32;
                    off2 += 7632 - (kk << 5);
                    kk   += 32;
                }
                mx = fmaxf(mx, tv[c]);
            }
            #pragma unroll
            for (int o = 16; o; o >>= 1)
                mx = fmaxf(mx, __shfl_xor_sync(0xffffffffu, mx, o));

            float acc = 0.f;
            #pragma unroll
            for (int c = 0; c < 8; ++c)
                if (c < nch) acc += __expf(tv[c] - mx);
            #pragma unroll
            for (int o = 16; o; o >>= 1)
                acc += __shfl_xor_sync(0xffffffffu, acc, o);

            // butterfly left mx/acc in every lane: lanes 0..15 broadcast to
            // one peer each (peer==rank is the local replica store).
            const float val = scij + mx + __logf(acc);
            if (lane < CLUSTER) {
                const uint32_t laddr = smem_u32(&s_tri[rb_i + (j - i - 1)]);
                st_peer(laddr, lane, val);
            }
        }
        cluster_sync_all();
    }

    // ---------------- backward init ----------------
    // zero lower triangle + diagonal of output (split across 16 CTAs)
    {
        const int base = (int)rank << 12;            // 4096 per CTA
        for (int idx = base + tid; idx < base + 4096; idx += NTHREADS) {
            const int i = idx >> 8;
            const int j = idx & 255;
            if (j <= i) mout[idx] = 0.f;
        }
    }
    if (rank == 0 && tid == 0) {
        const float s_top = s_tri[tri_base(0) + (SS - 2)];
        mout[SS - 1] = 1.0f;
        const float A = sc[SS - 1] - s_top;          // log g = 0
        __stcg(&g_Ar[b][0][SS - 1], A);
        __stcg(&g_Ac[b][SS - 1][0], A);
    }
    cluster_sync_all();

    // ---------------- backward widths 254..1 ----------------
    // g[a,bc] = sum_{j>bc} exp(s_ab + s[bc,j] + Ar[a][j])
    //         + sum_{i<a}  exp(s_ab + s[i,a]  + Ac[bc][i])
    for (int w = SS - 2; w >= 1; --w) {
        const int nspans = SS - w;
        const int sp = sp_of_warp;
        if (sp < nspans) {
            const int a  = sp;
            const int bc = a + w;
            const float s_ab = s_tri[tri_base(a) + (bc - a - 1)];
            const float scab = __ldca(&sc[a * SS + bc]);

            float acc = 0.f;

            // segment 1: parents (a, j), j = bc+1 .. S-1
            {
                const int rb_bc = tri_base(bc);
                const float* Ar = &g_Ar[b][a][0];
                for (int j = bc + 1 + lane; j < SS; j += 32) {
                    const float x = s_tri[rb_bc + (j - bc - 1)] + __ldcg(Ar + j);
                    acc += __expf(s_ab + x);
                }
            }
            // segment 2: parents (i, bc), i = 0 .. a-1
            {
                const float* Ac = &g_Ac[b][bc][0];
                int i   = lane;
                int off = tri_base(i) + (a - i - 1);
                while (i < a) {
                    acc += __expf(s_ab + s_tri[off] + __ldcg(Ac + i));
                    off += 7632 - (i << 5);
                    i   += 32;
                }
            }

            #pragma unroll
            for (int o = 16; o; o >>= 1)
                acc += __shfl_xor_sync(0xffffffffu, acc, o);

            if (lane == 0) {
                const float g = acc;
                mout[a * SS + bc] = g;
                const float A = __logf(g) + scab - s_ab;
                __stcg(&g_Ar[b][a][bc], A);
                __stcg(&g_Ac[b][bc][a], A);
            }
        }
        cluster_sync_all();
    }
}

extern "C" void kernel_launch(void* const* d_in, const int* in_sizes, int n_in,
                              void* d_out, int out_size)
{
    (void)in_sizes; (void)n_in; (void)out_size;
    const float* scores = (const float*)d_in[0];
    float* out = (float*)d_out;

    cudaFuncSetAttribute(crf_inside_outside_cluster,
                         cudaFuncAttributeMaxDynamicSharedMemorySize, SMEM_BYTES);
    cudaFuncSetAttribute(crf_inside_outside_cluster,
                         cudaFuncAttributeNonPortableClusterSizeAllowed, 1);
    crf_inside_outside_cluster<<<BB * CLUSTER, NTHREADS, SMEM_BYTES>>>(scores, out);
}

// round 11
// speedup vs baseline: 1.5715x; 1.5715x over previous
#include <cuda_runtime.h>
#include <cuda_bf16.h>
#include <cstdint>

// CRFConstituency inside-outside, B=8, S=256, lens==255 (fixed triu mask).
// R10: halo blocking. 8-CTA cluster per batch (grid=64, 1024 thr/CTA), full
// smem replica of the packed inside triangle per CTA. Span ownership is
// BLOCKED (CTA r owns starts [32r,32r+32)). MW=8 widths are processed per
// cluster sync; inside a block, sub-steps are separated only by __syncthreads.
// Each CTA redundantly computes a shrinking right-halo (forward) / left-halo
// (backward) of up to MW-1 extra spans so all in-block dependencies are
// CTA-local. At block end each owner broadcasts its new values to all peer
// replicas (st.shared::cluster), then one barrier.cluster.
// Cuts cluster syncs 509 -> 64 at ~11% redundant compute.

#define SS 256
#define BB 8
#define CLUSTER 8
#define NTHREADS 1024
#define MW 8
#define TRI ((SS*(SS-1))/2)          // 32640 floats
#define SMEM_BYTES (TRI*4)           // 130560 bytes dynamic
#define NEGF (-1e30f)

__device__ float g_Ar[BB][SS][SS];
__device__ float g_Ac[BB][SS][SS];

__device__ __forceinline__ int tri_base(int i) {
    return i * (SS - 1) - ((i * (i - 1)) >> 1);
}

__device__ __forceinline__ uint32_t smem_u32(const void* p) {
    uint32_t a;
    asm("{ .reg .u64 t; cvta.to.shared.u64 t, %1; cvt.u32.u64 %0, t; }"
        : "=r"(a) : "l"(p));
    return a;
}

__device__ __forceinline__ void st_peer(uint32_t local_addr, int peer, float v) {
    uint32_t rem;
    asm volatile("mapa.shared::cluster.u32 %0, %1, %2;"
                 : "=r"(rem) : "r"(local_addr), "r"(peer));
    asm volatile("st.shared::cluster.f32 [%0], %1;" :: "r"(rem), "f"(v));
}

__device__ __forceinline__ void cluster_sync_all() {
    asm volatile("barrier.cluster.arrive.aligned;" ::: "memory");
    asm volatile("barrier.cluster.wait.aligned;" ::: "memory");
}

__global__ __launch_bounds__(NTHREADS, 1) __cluster_dims__(CLUSTER, 1, 1)
void crf_inside_outside_halo(const float* __restrict__ scores,
                             float* __restrict__ out)
{
    extern __shared__ float s_tri[];     // full packed triangle replica

    const int b = blockIdx.x >> 3;       // cluster index = batch
    uint32_t rank;
    asm("mov.u32 %0, %%cluster_ctarank;" : "=r"(rank));

    const float* sc = scores + b * SS * SS;
    float* mout     = out    + b * SS * SS;

    const int tid  = threadIdx.x;
    const int lane = tid & 31;
    const int wid  = tid >> 5;           // 32 warps
    const int base = (int)rank << 5;     // owned span starts [base, base+32)

    // ---------------- forward width-1 init (local replica) ----------------
    for (int i = tid; i < SS - 1; i += NTHREADS)
        s_tri[tri_base(i)] = sc[i * SS + i + 1];
    __syncthreads();
    cluster_sync_all();

    // ---------------- forward widths 2..255 in blocks of MW ----------------
    for (int w0 = 2; w0 <= SS - 1; w0 += MW) {
        const int wtop = (w0 + MW - 1 < SS - 1) ? (w0 + MW - 1) : (SS - 1);

        for (int w = w0; w <= wtop; ++w) {
            const int hal = wtop - w;                 // halo width this sub-step
            const int hi0 = base + 32 + hal;
            const int hi  = (hi0 < SS - w) ? hi0 : (SS - w);
            const int nch = (w - 1 + 31) >> 5;

            for (int i = base + wid; i < hi; i += 32) {
                const int j = i + w;
                const int rb_i = tri_base(i);
                const float scij = __ldca(&sc[i * SS + j]);

                int k0   = i + 1 + lane;
                int off1 = rb_i + lane;
                int off2 = tri_base(k0) + (j - k0 - 1);
                int kk   = k0;

                float tv[8];
                float mx = NEGF;
                #pragma unroll
                for (int c = 0; c < 8; ++c) {
                    tv[c] = NEGF;
                    if (c < nch) {
                        if (kk < j)
                            tv[c] = s_tri[off1] + s_tri[off2];
                        off1 += 32;
                        off2 += 7632 - (kk << 5);
                        kk   += 32;
                    }
                    mx = fmaxf(mx, tv[c]);
                }
                #pragma unroll
                for (int o = 16; o; o >>= 1)
                    mx = fmaxf(mx, __shfl_xor_sync(0xffffffffu, mx, o));

                float acc = 0.f;
                #pragma unroll
                for (int c = 0; c < 8; ++c)
                    if (c < nch) acc += __expf(tv[c] - mx);
                #pragma unroll
                for (int o = 16; o; o >>= 1)
                    acc += __shfl_xor_sync(0xffffffffu, acc, o);

                if (lane == 0)
                    s_tri[rb_i + (w - 1)] = scij + mx + __logf(acc);
            }
            __syncthreads();
        }

        // broadcast owned spans of widths w0..wtop to the 7 peer replicas
        const int wcnt = wtop - w0 + 1;
        for (int idx = tid; idx < wcnt * 32; idx += NTHREADS) {
            const int t = idx >> 5;
            const int i = base + (idx & 31);
            const int w = w0 + t;
            if (i < SS - w) {
                const int off = tri_base(i) + (w - 1);
                const float val = s_tri[off];
                const uint32_t laddr = smem_u32(&s_tri[off]);
                #pragma unroll
                for (int p = 0; p < CLUSTER; ++p)
                    if (p != (int)rank) st_peer(laddr, p, val);
            }
        }
        cluster_sync_all();
    }

    // ---------------- backward init ----------------
    // zero lower triangle + diagonal of output (split across 8 CTAs)
    for (int idx = ((int)rank << 13) + tid; idx < (((int)rank + 1) << 13); idx += NTHREADS) {
        const int i = idx >> 8;
        const int j = idx & 255;
        if (j <= i) mout[idx] = 0.f;
    }
    if (rank == 0 && tid == 0) {
        const float s_top = s_tri[tri_base(0) + (SS - 2)];
        mout[SS - 1] = 1.0f;
        const float A = sc[SS - 1] - s_top;      // log g = 0
        __stcg(&g_Ar[b][0][SS - 1], A);
        __stcg(&g_Ac[b][SS - 1][0], A);
    }
    cluster_sync_all();

    // ---------------- backward widths 254..1 in blocks of MW ----------------
    // g[a,bc] = sum_{j>bc} exp(s_ab + s[bc,j] + Ar[a][j])
    //         + sum_{i<a}  exp(s_ab + s[i,a]  + Ac[bc][i])
    for (int w0 = SS - 2; w0 >= 1; w0 -= MW) {
        const int wbot = (w0 - MW + 1 > 1) ? (w0 - MW + 1) : 1;

        for (int w = w0; w >= wbot; --w) {
            const int hal = w - wbot;                 // halo width this sub-step
            const int lo0 = base - hal;
            const int lo  = (lo0 > 0) ? lo0 : 0;
            const int hi0 = base + 32;
            const int hi  = (hi0 < SS - w) ? hi0 : (SS - w);

            for (int a = lo + wid; a < hi; a += 32) {
                const int bc = a + w;
                const float s_ab = s_tri[tri_base(a) + (w - 1)];
                const float scab = __ldca(&sc[a * SS + bc]);

                float acc = 0.f;

                // segment 1: parents (a, j), j = bc+1 .. S-1
                {
                    const int rb_bc = tri_base(bc);
                    const float* Ar = &g_Ar[b][a][0];
                    for (int j = bc + 1 + lane; j < SS; j += 32) {
                        const float x = s_tri[rb_bc + (j - bc - 1)] + __ldcg(Ar + j);
                        acc += __expf(s_ab + x);
                    }
                }
                // segment 2: parents (i, bc), i = 0 .. a-1
                {
                    const float* Ac = &g_Ac[b][bc][0];
                    int i   = lane;
                    int off = tri_base(i) + (a - i - 1);
                    while (i < a) {
                        acc += __expf(s_ab + s_tri[off] + __ldcg(Ac + i));
                        off += 7632 - (i << 5);
                        i   += 32;
                    }
                }

                #pragma unroll
                for (int o = 16; o; o >>= 1)
                    acc += __shfl_xor_sync(0xffffffffu, acc, o);

                if (lane == 0) {
                    const float g = acc;
                    mout[a * SS + bc] = g;
                    const float A = __logf(g) + scab - s_ab;
                    __stcg(&g_Ar[b][a][bc], A);
                    __stcg(&g_Ac[b][bc][a], A);
                }
            }
            __syncthreads();
        }
        cluster_sync_all();
    }
}

extern "C" void kernel_launch(void* const* d_in, const int* in_sizes, int n_in,
                              void* d_out, int out_size)
{
    (void)in_sizes; (void)n_in; (void)out_size;
    const float* scores = (const float*)d_in[0];
    float* out = (float*)d_out;

    cudaFuncSetAttribute(crf_inside_outside_halo,
                         cudaFuncAttributeMaxDynamicSharedMemorySize, SMEM_BYTES);
    crf_inside_outside_halo<<<BB * CLUSTER, NTHREADS, SMEM_BYTES>>>(scores, out);
}

// round 13
// speedup vs baseline: 1.7275x; 1.0993x over previous
#include <cuda_runtime.h>
#include <cuda_bf16.h>
#include <cstdint>

// CRFConstituency inside-outside, B=8, S=256, lens==255 (fixed triu mask).
// R13 = R10 halo blocking (8-CTA cluster/batch, 1024 thr, full smem replica,
// MW=8 widths per barrier.cluster) plus:
//  - warp max via redux.sync.max.s32 on the monotone float<->int embedding
//    (sm_103 has no redux.f32) -- replaces a 5-step SHFL butterfly.
//  - early-break chunk loops (no dead predicated chunks at narrow widths).
// Sum reductions remain SHFL butterflies (no integer trick for FP add).

#define SS 256
#define BB 8
#define CLUSTER 8
#define NTHREADS 1024
#define MW 8
#define TRI ((SS*(SS-1))/2)          // 32640 floats
#define SMEM_BYTES (TRI*4)           // 130560 bytes dynamic
#define NEGF (-1e30f)

__device__ float g_Ar[BB][SS][SS];
__device__ float g_Ac[BB][SS][SS];

__device__ __forceinline__ int tri_base(int i) {
    return i * (SS - 1) - ((i * (i - 1)) >> 1);
}

__device__ __forceinline__ uint32_t smem_u32(const void* p) {
    uint32_t a;
    asm("{ .reg .u64 t; cvta.to.shared.u64 t, %1; cvt.u32.u64 %0, t; }"
        : "=r"(a) : "l"(p));
    return a;
}

__device__ __forceinline__ void st_peer(uint32_t local_addr, int peer, float v) {
    uint32_t rem;
    asm volatile("mapa.shared::cluster.u32 %0, %1, %2;"
                 : "=r"(rem) : "r"(local_addr), "r"(peer));
    asm volatile("st.shared::cluster.f32 [%0], %1;" :: "r"(rem), "f"(v));
}

__device__ __forceinline__ void cluster_sync_all() {
    asm volatile("barrier.cluster.arrive.aligned;" ::: "memory");
    asm volatile("barrier.cluster.wait.aligned;" ::: "memory");
}

// warp-wide fp32 max via integer redux: for finite floats the map
// i>=0 ? i : i^0x7fffffff is monotone float->s32.
__device__ __forceinline__ float warp_max_f32(float v) {
    int i = __float_as_int(v);
    i = (i >= 0) ? i : (i ^ 0x7fffffff);
    int r;
    asm volatile("redux.sync.max.s32 %0, %1, 0xffffffff;" : "=r"(r) : "r"(i));
    r = (r >= 0) ? r : (r ^ 0x7fffffff);
    return __int_as_float(r);
}

__device__ __forceinline__ float warp_sum_f32(float v) {
    #pragma unroll
    for (int o = 16; o; o >>= 1)
        v += __shfl_xor_sync(0xffffffffu, v, o);
    return v;
}

__global__ __launch_bounds__(NTHREADS, 1) __cluster_dims__(CLUSTER, 1, 1)
void crf_inside_outside_halo(const float* __restrict__ scores,
                             float* __restrict__ out)
{
    extern __shared__ float s_tri[];     // full packed triangle replica

    const int b = blockIdx.x >> 3;       // cluster index = batch
    uint32_t rank;
    asm("mov.u32 %0, %%cluster_ctarank;" : "=r"(rank));

    const float* sc = scores + b * SS * SS;
    float* mout     = out    + b * SS * SS;

    const int tid  = threadIdx.x;
    const int lane = tid & 31;
    const int wid  = tid >> 5;           // 32 warps
    const int base = (int)rank << 5;     // owned span starts [base, base+32)

    // ---------------- forward width-1 init (local replica) ----------------
    for (int i = tid; i < SS - 1; i += NTHREADS)
        s_tri[tri_base(i)] = sc[i * SS + i + 1];
    __syncthreads();
    cluster_sync_all();

    // ---------------- forward widths 2..255 in blocks of MW ----------------
    for (int w0 = 2; w0 <= SS - 1; w0 += MW) {
        const int wtop = (w0 + MW - 1 < SS - 1) ? (w0 + MW - 1) : (SS - 1);

        for (int w = w0; w <= wtop; ++w) {
            const int hal = wtop - w;                 // halo width this sub-step
            const int hi0 = base + 32 + hal;
            const int hi  = (hi0 < SS - w) ? hi0 : (SS - w);
            const int nch = (w - 1 + 31) >> 5;

            for (int i = base + wid; i < hi; i += 32) {
                const int j = i + w;
                const int rb_i = tri_base(i);
                const float scij = __ldca(&sc[i * SS + j]);

                int k0   = i + 1 + lane;
                int off1 = rb_i + lane;
                int off2 = tri_base(k0) + (j - k0 - 1);
                int kk   = k0;

                float tv[8];
                float mx = NEGF;
                #pragma unroll
                for (int c = 0; c < 8; ++c) {
                    if (c >= nch) break;              // early exit, not predication
                    tv[c] = (kk < j) ? (s_tri[off1] + s_tri[off2]) : NEGF;
                    mx = fmaxf(mx, tv[c]);
                    off1 += 32;
                    off2 += 7632 - (kk << 5);
                    kk   += 32;
                }
                mx = warp_max_f32(mx);

                float acc = 0.f;
                #pragma unroll
                for (int c = 0; c < 8; ++c) {
                    if (c >= nch) break;
                    acc += __expf(tv[c] - mx);
                }
                acc = warp_sum_f32(acc);

                if (lane == 0)
                    s_tri[rb_i + (w - 1)] = scij + mx + __logf(acc);
            }
            __syncthreads();
        }

        // broadcast owned spans of widths w0..wtop to the 7 peer replicas
        const int wcnt = wtop - w0 + 1;
        for (int idx = tid; idx < wcnt * 32; idx += NTHREADS) {
            const int t = idx >> 5;
            const int i = base + (idx & 31);
            const int w = w0 + t;
            if (i < SS - w) {
                const int off = tri_base(i) + (w - 1);
                const float val = s_tri[off];
                const uint32_t laddr = smem_u32(&s_tri[off]);
                #pragma unroll
                for (int p = 0; p < CLUSTER; ++p)
                    if (p != (int)rank) st_peer(laddr, p, val);
            }
        }
        cluster_sync_all();
    }

    // ---------------- backward init ----------------
    for (int idx = ((int)rank << 13) + tid; idx < (((int)rank + 1) << 13); idx += NTHREADS) {
        const int i = idx >> 8;
        const int j = idx & 255;
        if (j <= i) mout[idx] = 0.f;
    }
    if (rank == 0 && tid == 0) {
        const float s_top = s_tri[tri_base(0) + (SS - 2)];
        mout[SS - 1] = 1.0f;
        const float A = sc[SS - 1] - s_top;      // log g = 0
        __stcg(&g_Ar[b][0][SS - 1], A);
        __stcg(&g_Ac[b][SS - 1][0], A);
    }
    cluster_sync_all();

    // ---------------- backward widths 254..1 in blocks of MW ----------------
    // g[a,bc] = sum_{j>bc} exp(s_ab + s[bc,j] + Ar[a][j])
    //         + sum_{i<a}  exp(s_ab + s[i,a]  + Ac[bc][i])
    for (int w0 = SS - 2; w0 >= 1; w0 -= MW) {
        const int wbot = (w0 - MW + 1 > 1) ? (w0 - MW + 1) : 1;

        for (int w = w0; w >= wbot; --w) {
            const int hal = w - wbot;                 // halo width this sub-step
            const int lo0 = base - hal;
            const int lo  = (lo0 > 0) ? lo0 : 0;
            const int hi0 = base + 32;
            const int hi  = (hi0 < SS - w) ? hi0 : (SS - w);

            for (int a = lo + wid; a < hi; a += 32) {
                const int bc = a + w;
                const float s_ab = s_tri[tri_base(a) + (w - 1)];
                const float scab = __ldca(&sc[a * SS + bc]);

                float acc = 0.f;

                // segment 1: parents (a, j), j = bc+1 .. S-1
                {
                    const int rb_bc = tri_base(bc);
                    const float* Ar = &g_Ar[b][a][0];
                    for (int j = bc + 1 + lane; j < SS; j += 32) {
                        const float x = s_tri[rb_bc + (j - bc - 1)] + __ldcg(Ar + j);
                        acc += __expf(s_ab + x);
                    }
                }
                // segment 2: parents (i, bc), i = 0 .. a-1
                {
                    const float* Ac = &g_Ac[b][bc][0];
                    int i   = lane;
                    int off = tri_base(i) + (a - i - 1);
                    while (i < a) {
                        acc += __expf(s_ab + s_tri[off] + __ldcg(Ac + i));
                        off += 7632 - (i << 5);
                        i   += 32;
                    }
                }

                acc = warp_sum_f32(acc);

                if (lane == 0) {
                    const float g = acc;
                    mout[a * SS + bc] = g;
                    const float A = __logf(g) + scab - s_ab;
                    __stcg(&g_Ar[b][a][bc], A);
                    __stcg(&g_Ac[b][bc][a], A);
                }
            }
            __syncthreads();
        }
        cluster_sync_all();
    }
}

extern "C" void kernel_launch(void* const* d_in, const int* in_sizes, int n_in,
                              void* d_out, int out_size)
{
    (void)in_sizes; (void)n_in; (void)out_size;
    const float* scores = (const float*)d_in[0];
    float* out = (float*)d_out;

    cudaFuncSetAttribute(crf_inside_outside_halo,
                         cudaFuncAttributeMaxDynamicSharedMemorySize, SMEM_BYTES);
    crf_inside_outside_halo<<<BB * CLUSTER, NTHREADS, SMEM_BYTES>>>(scores, out);
}